// round 3
// baseline (speedup 1.0000x reference)
#include <cuda_runtime.h>
#include <math.h>

#define BATCH  32
#define TLEN   2048
#define HE     1024
#define CHUNKS 8
#define ROWS_PER_CTA (TLEN / CHUNKS)   // 256
#define STAGE  16
#define NSTAGES (ROWS_PER_CTA / STAGE) // 16
#define THREADS 256

// Cross-CTA partials (allocation-free scratch)
__device__ float g_pm[BATCH * CHUNKS];
__device__ float g_pz[BATCH * CHUNKS];
__device__ float g_pacc[BATCH * CHUNKS * HE];

__global__ __launch_bounds__(THREADS)
void attn_partial_kernel(const float* __restrict__ hidden,   // (2,32,1024)
                         const float* __restrict__ enc,      // (32,2048,1024)
                         const float* __restrict__ mask,     // (32,2048)
                         const float* __restrict__ attn_w,   // (3072,)
                         const float* __restrict__ attn_b)   // (1,)
{
    __shared__ float s_we[HE];
    __shared__ float s_e[STAGE];
    __shared__ float s_mk[STAGE];
    __shared__ float s_red[THREADS / 32];
    __shared__ float s_hb;

    const int tid   = threadIdx.x;
    const int b     = blockIdx.y;
    const int chunk = blockIdx.x;
    const int lane  = tid & 31;
    const int warp  = tid >> 5;

    // stage w_e (attn_w[2048:3072]) into smem
    for (int i = tid; i < HE; i += THREADS) s_we[i] = attn_w[2048 + i];

    // hb = hid_flat[b] . w_h + bias ; hid_flat[b, j*1024+k] = hidden[j, b, k]
    float hsum = 0.f;
    for (int i = tid; i < 2048; i += THREADS) {
        int j = i >> 10, k = i & 1023;
        hsum += hidden[(size_t)j * BATCH * HE + (size_t)b * HE + k] * attn_w[i];
    }
    #pragma unroll
    for (int o = 16; o; o >>= 1) hsum += __shfl_xor_sync(0xffffffffu, hsum, o);
    if (lane == 0) s_red[warp] = hsum;
    __syncthreads();
    if (tid == 0) {
        float s = 0.f;
        #pragma unroll
        for (int w = 0; w < THREADS / 32; w++) s += s_red[w];
        s_hb = s + attn_b[0];
    }
    __syncthreads();
    const float hb = s_hb;

    const float4* we4  = (const float4*)s_we;
    const int     t0   = chunk * ROWS_PER_CTA;
    const float*  mrow = mask + (size_t)b * TLEN;

    float  m = -INFINITY, z = 0.f;
    float4 acc = make_float4(0.f, 0.f, 0.f, 0.f);

    for (int stage = 0; stage < NSTAGES; stage++) {
        const int bt = t0 + stage * STAGE;

        // ---- energy phase: each warp computes 2 of the 16 rows ----
        #pragma unroll
        for (int rr = 0; rr < 2; rr++) {
            const int r = warp + rr * 8;
            const int t = bt + r;
            const float4* row4 = (const float4*)(enc + ((size_t)b * TLEN + t) * HE);
            float s = 0.f;
            #pragma unroll
            for (int i = 0; i < 8; i++) {
                float4 v = row4[lane + 32 * i];
                float4 w = we4[lane + 32 * i];
                s += v.x * w.x + v.y * w.y + v.z * w.z + v.w * w.w;
            }
            #pragma unroll
            for (int o = 16; o; o >>= 1) s += __shfl_xor_sync(0xffffffffu, s, o);
            if (lane == 0) {
                float mk = mrow[t];
                s_e[r]  = (s + hb) * mk;   // reference: energies *= mask BEFORE softmax
                s_mk[r] = mk;
            }
        }
        __syncthreads();

        // ---- online softmax update (replicated scalars, all threads identical) ----
        float smax = s_e[0];
        #pragma unroll
        for (int r = 1; r < STAGE; r++) smax = fmaxf(smax, s_e[r]);
        const float m_new  = fmaxf(m, smax);
        const float factor = __expf(m - m_new);   // m = -inf on first stage -> 0
        acc.x *= factor; acc.y *= factor; acc.z *= factor; acc.w *= factor;
        z *= factor;

        float wr[STAGE];
        #pragma unroll
        for (int r = 0; r < STAGE; r++) {
            wr[r] = __expf(s_e[r] - m_new) * s_mk[r];  // reference: *= mask AFTER softmax
            z += wr[r];
        }
        m = m_new;

        // ---- accumulate phase: rows re-read (L1/L2 hits), thread owns 4 cols ----
        const float4* base = (const float4*)(enc + ((size_t)b * TLEN + bt) * HE);
        #pragma unroll 4
        for (int r = 0; r < STAGE; r++) {
            float4 v = base[(size_t)r * (HE / 4) + tid];
            acc.x += wr[r] * v.x; acc.y += wr[r] * v.y;
            acc.z += wr[r] * v.z; acc.w += wr[r] * v.w;
        }
        __syncthreads();   // protect s_e/s_mk before next stage overwrites
    }

    const int pidx = b * CHUNKS + chunk;
    if (tid == 0) { g_pm[pidx] = m; g_pz[pidx] = z; }
    ((float4*)(g_pacc + (size_t)pidx * HE))[tid] = acc;
}

__global__ __launch_bounds__(THREADS)
void attn_combine_kernel(float* __restrict__ out)  // (32, 1024)
{
    const int b   = blockIdx.x;
    const int tid = threadIdx.x;

    float M = -INFINITY;
    #pragma unroll
    for (int c = 0; c < CHUNKS; c++) M = fmaxf(M, g_pm[b * CHUNKS + c]);

    float Z = 0.f;
    float f[CHUNKS];
    #pragma unroll
    for (int c = 0; c < CHUNKS; c++) {
        f[c] = __expf(g_pm[b * CHUNKS + c] - M);
        Z += f[c] * g_pz[b * CHUNKS + c];
    }
    const float inv = 1.f / Z;

    float4 o = make_float4(0.f, 0.f, 0.f, 0.f);
    #pragma unroll
    for (int c = 0; c < CHUNKS; c++) {
        float4 a = ((const float4*)(g_pacc + (size_t)(b * CHUNKS + c) * HE))[tid];
        o.x += f[c] * a.x; o.y += f[c] * a.y;
        o.z += f[c] * a.z; o.w += f[c] * a.w;
    }
    o.x *= inv; o.y *= inv; o.z *= inv; o.w *= inv;
    ((float4*)(out + (size_t)b * HE))[tid] = o;
}

extern "C" void kernel_launch(void* const* d_in, const int* in_sizes, int n_in,
                              void* d_out, int out_size)
{
    const float* hidden = (const float*)d_in[0];  // (2,32,1024)
    const float* enc    = (const float*)d_in[1];  // (32,2048,1024)
    const float* mask   = (const float*)d_in[2];  // (32,2048)
    const float* attn_w = (const float*)d_in[3];  // (3072,)
    const float* attn_b = (const float*)d_in[4];  // (1,)
    float* out = (float*)d_out;                   // (32,1024)

    dim3 grid(CHUNKS, BATCH);
    attn_partial_kernel<<<grid, THREADS>>>(hidden, enc, mask, attn_w, attn_b);
    attn_combine_kernel<<<BATCH, THREADS>>>(out);
}